// round 10
// baseline (speedup 1.0000x reference)
#include <cuda_runtime.h>
#include <cuda_fp16.h>
#include <cstdint>
#include <cstddef>

#define NB 8
#define CI 256
#define CO 256
#define NL 512
#define NPIX (8*128*128)
#define NTILES 32768            // 8 * 64 * 64 winograd tiles
#define HTILES 16384            // tiles per batch-half
#define HPIX (NPIX/2)

#define C_STD  0.0625f
#define C_CONV 0.02946278254943948f
#define C_D1   0.08838834764831845f
#define C_D2   0.04419417382415922f

// ---------------- scratch --------------------------------------------------
__device__ float  g_s[NB*CI];
__device__ float  g_d[NB*CO];
__device__ int    g_nflag;
__device__ __half g_U[(size_t)16*CO*CI];        // winograd weights [p][co][ci]
__device__ __half g_V[(size_t)16*NTILES*CI];    // winograd input  [p][tile][ci]
__device__ __half g_w1T[4*CO*CO];               // D1 w [n=1024][k=256]
__device__ __half g_w2T[(size_t)CO*4*CO];       // D2 w [n=256][k=1024]
__device__ __half g_y[(size_t)NPIX*CO];         // conv out (post-lrelu)
__device__ __half g_h[(size_t)NPIX*4*CO];       // D1 out; ALSO aliased as M [tile][p][co]

// ---------------- helpers --------------------------------------------------
__device__ __forceinline__ float lrelu(float x){ return x > 0.f ? x : 0.2f*x; }

__device__ __forceinline__ void mma16(float c[4], const uint32_t a[4], const uint32_t b[2]){
    asm volatile("mma.sync.aligned.m16n8k16.row.col.f32.f16.f16.f32 "
        "{%0,%1,%2,%3}, {%4,%5,%6,%7}, {%8,%9}, {%0,%1,%2,%3};\n"
        : "+f"(c[0]), "+f"(c[1]), "+f"(c[2]), "+f"(c[3])
        : "r"(a[0]), "r"(a[1]), "r"(a[2]), "r"(a[3]), "r"(b[0]), "r"(b[1]));
}
__device__ __forceinline__ void ldsm4(uint32_t& r0, uint32_t& r1, uint32_t& r2,
                                      uint32_t& r3, uint32_t addr){
    asm volatile("ldmatrix.sync.aligned.m8n8.x4.shared.b16 {%0,%1,%2,%3}, [%4];"
        : "=r"(r0), "=r"(r1), "=r"(r2), "=r"(r3) : "r"(addr));
}
__device__ __forceinline__ void cp16(uint32_t d, const void* s, int nbytes){
    asm volatile("cp.async.ca.shared.global [%0], [%1], 16, %2;\n"
                 :: "r"(d), "l"(s), "r"(nbytes));
}
__device__ __forceinline__ void cp_commit(){ asm volatile("cp.async.commit_group;\n"); }
template<int N> __device__ __forceinline__ void cp_wait(){
    asm volatile("cp.async.wait_group %0;\n" :: "n"(N));
}

// ---------------- tile layout ----------------------------------------------
struct Tiles {
    __half A[128][72];
    __half Bt[128][72];
};

__device__ __forceinline__ void compute_tile(const Tiles& t, float acc[2][8][4],
                                             int wm, int wn, int lane){
    uint32_t aBase = (uint32_t)__cvta_generic_to_shared(&t.A[0][0]);
    uint32_t bBase = (uint32_t)__cvta_generic_to_shared(&t.Bt[0][0]);
    uint32_t aOff = aBase + (uint32_t)(((wm*32 + (lane & 15))*72 + (lane >> 4)*8)*2);
    int g = lane >> 3;
    uint32_t bOff = bBase + (uint32_t)(((wn*64 + (g >> 1)*8 + (lane & 7))*72 + (g & 1)*8)*2);
#pragma unroll
    for (int kk = 0; kk < 4; kk++){
        uint32_t a[2][4];
#pragma unroll
        for (int mt = 0; mt < 2; mt++)
            ldsm4(a[mt][0], a[mt][1], a[mt][2], a[mt][3],
                  aOff + kk*32 + mt*(16*72*2));
        uint32_t b[8][2];
#pragma unroll
        for (int nt2 = 0; nt2 < 4; nt2++){
            uint32_t r0, r1, r2, r3;
            ldsm4(r0, r1, r2, r3, bOff + kk*32 + nt2*(16*72*2));
            b[2*nt2][0] = r0; b[2*nt2][1] = r1;
            b[2*nt2+1][0] = r2; b[2*nt2+1][1] = r3;
        }
#pragma unroll
        for (int mt = 0; mt < 2; mt++)
#pragma unroll
            for (int nt = 0; nt < 8; nt++)
                mma16(acc[mt][nt], a[mt], b[nt]);
    }
}

// ---------------- prep kernels ---------------------------------------------
__global__ void s_kernel(const float* __restrict__ latent,
                         const float* __restrict__ stdW,
                         const float* __restrict__ stdb){
    if (blockIdx.x == 0 && threadIdx.x == 0) g_nflag = 0;
    int b = blockIdx.x, i = threadIdx.x;
    float acc = 0.f;
    for (int l = 0; l < NL; l++) acc += latent[b*NL+l] * stdW[l*CI+i];
    g_s[b*CI+i] = acc * C_STD + stdb[i];
}

__global__ void d_kernel(const float* __restrict__ cw, const float* __restrict__ ncoef){
    int b = blockIdx.x, o = threadIdx.x;
    if (b == 0 && ncoef[o] != 0.f) atomicOr(&g_nflag, 1);
    float acc = 0.f;
    for (int i = 0; i < CI; i++){
        float w2 = 0.f;
#pragma unroll
        for (int k = 0; k < 9; k++){
            float wv = cw[(size_t)(k*CI + i)*CO + o];
            w2 += wv*wv;
        }
        float sv = g_s[b*CI+i];
        acc += w2 * sv * sv;
    }
    g_d[b*CO+o] = rsqrtf(acc * (C_CONV*C_CONV) + 1e-8f);
}

__device__ __forceinline__ void tblock(const float* src, __half* dst,
                                       int R, int C, float sc, int r0, int c0){
    __shared__ float t[32][33];
    int x = threadIdx.x, y = threadIdx.y;   // 32 x 8
#pragma unroll
    for (int i = 0; i < 32; i += 8)
        t[y+i][x] = src[(size_t)(r0+y+i)*C + c0+x];
    __syncthreads();
#pragma unroll
    for (int i = 0; i < 32; i += 8)
        dst[(size_t)(c0+y+i)*R + r0+x] = __float2half_rn(t[x][y+i]*sc);
}
__global__ void tscale_d12(const float* __restrict__ d1w, const float* __restrict__ d2w,
                           __half* __restrict__ w1, __half* __restrict__ w2){
    if (blockIdx.z == 0){
        tblock(d1w, w1, 256, 1024, C_D1, blockIdx.y*32, blockIdx.x*32);
    } else {
        int flat = blockIdx.x + blockIdx.y*32;
        tblock(d2w, w2, 1024, 256, C_D2, (flat/8)*32, (flat%8)*32);
    }
}

// ---------------- winograd weight transform: U = G g G^T --------------------
__global__ void wtrans(const float* __restrict__ cw){
    __shared__ float sg[9][32][33];      // [tap][ci][co]
    int ci0 = blockIdx.x*32, co0 = blockIdx.y*32;
    int x = threadIdx.x, y = threadIdx.y;
    int tid = y*32 + x;
#pragma unroll
    for (int k = 0; k < 9; k++)
#pragma unroll
        for (int i = 0; i < 32; i += 8)
            sg[k][y+i][x] = cw[((size_t)(k*256 + ci0 + y + i))*256 + co0 + x];
    __syncthreads();
#pragma unroll
    for (int j = 0; j < 4; j++){
        int pair = tid + j*256;
        int ci = pair & 31, co = pair >> 5;
        float g[3][3];
#pragma unroll
        for (int r = 0; r < 3; r++)
#pragma unroll
            for (int c = 0; c < 3; c++)
                g[r][c] = sg[r*3+c][ci][co] * C_CONV;
        float t[4][3];
#pragma unroll
        for (int c = 0; c < 3; c++){
            t[0][c] = g[0][c];
            t[1][c] = 0.5f*(g[0][c] + g[1][c] + g[2][c]);
            t[2][c] = 0.5f*(g[0][c] - g[1][c] + g[2][c]);
            t[3][c] = g[2][c];
        }
#pragma unroll
        for (int r = 0; r < 4; r++){
            float u0 = t[r][0];
            float u1 = 0.5f*(t[r][0] + t[r][1] + t[r][2]);
            float u2 = 0.5f*(t[r][0] - t[r][1] + t[r][2]);
            float u3 = t[r][2];
            int p = r*4;
            g_U[((size_t)(p+0)*256 + co0+co)*256 + ci0+ci] = __float2half_rn(u0);
            g_U[((size_t)(p+1)*256 + co0+co)*256 + ci0+ci] = __float2half_rn(u1);
            g_U[((size_t)(p+2)*256 + co0+co)*256 + ci0+ci] = __float2half_rn(u2);
            g_U[((size_t)(p+3)*256 + co0+co)*256 + ci0+ci] = __float2half_rn(u3);
        }
    }
}

// ------- winograd input transform fused with modulation: V = B^T (x*s) B ----
// grid (64, 256) per half; yoff selects half. 256 threads = ci.
__global__ void vtrans(const float* __restrict__ data, int yoff){
    int ci = threadIdx.x;
    int tx = blockIdx.x;
    int by = blockIdx.y + yoff;
    int b = by >> 6, ty = by & 63;
    size_t t = (size_t)by*64 + tx;
    float sv = g_s[b*256 + ci];
    int ir0 = 2*ty - 1, ic0 = 2*tx - 1;
    float d[4][4];
#pragma unroll
    for (int r = 0; r < 4; r++){
        int ir = ir0 + r;
        bool rv = (unsigned)ir < 128u;
#pragma unroll
        for (int c = 0; c < 4; c++){
            int ic = ic0 + c;
            bool v = rv && ((unsigned)ic < 128u);
            d[r][c] = v ? data[((size_t)((b*128+ir)*128 + ic))*256 + ci] * sv : 0.f;
        }
    }
    float w[4][4];
#pragma unroll
    for (int c = 0; c < 4; c++){
        w[0][c] = d[0][c] - d[2][c];
        w[1][c] = d[1][c] + d[2][c];
        w[2][c] = d[2][c] - d[1][c];
        w[3][c] = d[1][c] - d[3][c];
    }
#pragma unroll
    for (int r = 0; r < 4; r++){
        float v0 = w[r][0] - w[r][2];
        float v1 = w[r][1] + w[r][2];
        float v2 = w[r][2] - w[r][1];
        float v3 = w[r][1] - w[r][3];
        int p = r*4;
        g_V[((size_t)(p+0)*NTILES + t)*256 + ci] = __float2half_rn(v0);
        g_V[((size_t)(p+1)*NTILES + t)*256 + ci] = __float2half_rn(v1);
        g_V[((size_t)(p+2)*NTILES + t)*256 + ci] = __float2half_rn(v2);
        g_V[((size_t)(p+3)*NTILES + t)*256 + ci] = __float2half_rn(v3);
    }
}

// ---------------- winograd output transform + epilogue ----------------------
// grid (64, 256) per half. M layout [tile][p][co] aliased in g_h.
__global__ void otrans(const float* __restrict__ bias, const float* __restrict__ noise,
                       const float* __restrict__ ncoef, int yoff){
    int co = threadIdx.x;
    int tx = blockIdx.x;
    int by = blockIdx.y + yoff;
    int b = by >> 6, ty = by & 63;
    size_t t = (size_t)by*64 + tx;
    int nflag = g_nflag;
    float m[4][4];
#pragma unroll
    for (int p = 0; p < 16; p++)
        m[p>>2][p&3] = __half2float(g_h[t*4096 + (size_t)p*256 + co]);
    float z[2][4];
#pragma unroll
    for (int c = 0; c < 4; c++){
        z[0][c] = m[0][c] + m[1][c] + m[2][c];
        z[1][c] = m[1][c] - m[2][c] - m[3][c];
    }
    float dv = g_d[b*256 + co];
    float bv = bias[co];
    float cv = nflag ? ncoef[co] : 0.f;
#pragma unroll
    for (int r = 0; r < 2; r++){
        float y0 = z[r][0] + z[r][1] + z[r][2];
        float y1 = z[r][1] - z[r][2] - z[r][3];
        int row = 2*ty + r;
#pragma unroll
        for (int c = 0; c < 2; c++){
            float yv = (c == 0) ? y0 : y1;
            int col = 2*tx + c;
            size_t pix = (size_t)(b*128 + row)*128 + col;
            float o = yv*dv + bv;
            if (nflag) o += noise[pix*256 + co] * cv;
            o = lrelu(o);
            g_y[pix*256 + co] = __float2half_rn(o);
        }
    }
}

// ---------------- generic GEMM (K64, 2-stage; EPI 0=winograd M, 1=D1, 2=D2) -
template<int K>
__device__ __forceinline__ void issue_gemm(Tiles* t, const __half* A, const __half* Bw,
                                           size_t m0, int n0, int s, int tid){
#pragma unroll
    for (int j = 0; j < 4; j++){
        int lin = tid + j*256;
        int r = lin >> 3, c8 = (lin & 7) * 8;
        cp16((uint32_t)__cvta_generic_to_shared(&t->A[r][c8]),
             A + (m0 + r)*(size_t)K + s*64 + c8, 16);
        cp16((uint32_t)__cvta_generic_to_shared(&t->Bt[r][c8]),
             Bw + (size_t)(n0 + r)*K + s*64 + c8, 16);
    }
}

template<int K, int N, int EPI>
__global__ void __launch_bounds__(256,2) gemm_kernel(
    const __half* __restrict__ A, const __half* __restrict__ Bw,
    const float* __restrict__ bias, void* __restrict__ outv)
{
    extern __shared__ Tiles tiles[];
    int tid = threadIdx.x;
    size_t m0 = (size_t)blockIdx.y * 128;
    int n0 = blockIdx.x * 128;
    size_t zp = 0;
    if (EPI == 0){
        zp = blockIdx.z;
        A  += zp * ((size_t)NTILES*256);
        Bw += zp * (256*256);
    }
    int wid = tid >> 5, lane = tid & 31;
    int wm = wid >> 1, wn = wid & 1, qr = lane >> 2, qc = lane & 3;

    float acc[2][8][4];
#pragma unroll
    for (int i = 0; i < 2; i++)
#pragma unroll
        for (int j = 0; j < 8; j++)
#pragma unroll
            for (int k = 0; k < 4; k++) acc[i][j][k] = 0.f;

    const int NK = K/64;
    issue_gemm<K>(&tiles[0], A, Bw, m0, n0, 0, tid); cp_commit();
#pragma unroll 1
    for (int s = 0; s < NK; s++){
        cp_wait<0>();
        __syncthreads();
        if (s + 1 < NK){ issue_gemm<K>(&tiles[(s+1)&1], A, Bw, m0, n0, s+1, tid); cp_commit(); }
        compute_tile(tiles[s&1], acc, wm, wn, lane);
    }

#pragma unroll
    for (int mt = 0; mt < 2; mt++){
#pragma unroll
        for (int nt = 0; nt < 8; nt++){
            int col = n0 + wn*64 + nt*8 + 2*qc;
            float b0 = (EPI != 0) ? bias[col]   : 0.f;
            float b1 = (EPI != 0) ? bias[col+1] : 0.f;
#pragma unroll
            for (int r2 = 0; r2 < 2; r2++){
                size_t m = m0 + wm*32 + mt*16 + qr + r2*8;
                float v0 = acc[mt][nt][r2*2+0];
                float v1 = acc[mt][nt][r2*2+1];
                if (EPI != 0){ v0 = lrelu(v0 + b0); v1 = lrelu(v1 + b1); }
                if (EPI == 2){
                    *(float2*)((float*)outv + m*(size_t)N + col) = make_float2(v0, v1);
                } else {
                    __half2 hv = __floats2half2_rn(v0, v1);
                    size_t oidx = (EPI == 0) ? ((m*16 + zp)*256 + col)
                                             : (m*(size_t)N + col);
                    *(uint32_t*)((__half*)outv + oidx) = *(uint32_t*)&hv;
                }
            }
        }
    }
}

// ---------------- launch ----------------------------------------------------
extern "C" void kernel_launch(void* const* d_in, const int* in_sizes, int n_in,
                              void* d_out, int out_size){
    const float* data   = (const float*)d_in[0];
    const float* latent = (const float*)d_in[1];
    const float* noise  = (const float*)d_in[2];
    const float* stdW   = (const float*)d_in[3];
    const float* stdb   = (const float*)d_in[4];
    const float* convw  = (const float*)d_in[5];
    const float* bias   = (const float*)d_in[6];
    const float* ncoef  = (const float*)d_in[7];
    const float* d1w    = (const float*)d_in[8];
    const float* d1b    = (const float*)d_in[9];
    const float* d2w    = (const float*)d_in[10];
    const float* d2b    = (const float*)d_in[11];
    float* out = (float*)d_out;

    void *p_U, *p_V, *p_w1, *p_w2, *p_y, *p_h;
    cudaGetSymbolAddress(&p_U,  g_U);
    cudaGetSymbolAddress(&p_V,  g_V);
    cudaGetSymbolAddress(&p_w1, g_w1T);
    cudaGetSymbolAddress(&p_w2, g_w2T);
    cudaGetSymbolAddress(&p_y,  g_y);
    cudaGetSymbolAddress(&p_h,  g_h);
    const __half* V  = (const __half*)p_V;
    const __half* U  = (const __half*)p_U;
    __half* Y  = (__half*)p_y;
    __half* Hh = (__half*)p_h;

    int smem = (int)sizeof(Tiles) * 2;   // 73728 B
    static bool init = false;
    static cudaStream_t s1;
    static cudaEvent_t ev[7];
    if (!init){
        cudaStreamCreateWithFlags(&s1, cudaStreamNonBlocking);
        for (int i = 0; i < 7; i++) cudaEventCreateWithFlags(&ev[i], cudaEventDisableTiming);
        cudaFuncSetAttribute(gemm_kernel<256,256,0>,  cudaFuncAttributeMaxDynamicSharedMemorySize, smem);
        cudaFuncSetAttribute(gemm_kernel<256,1024,1>, cudaFuncAttributeMaxDynamicSharedMemorySize, smem);
        cudaFuncSetAttribute(gemm_kernel<1024,256,2>, cudaFuncAttributeMaxDynamicSharedMemorySize, smem);
        init = true;
    }

    // ---- preps on S0 ----
    s_kernel<<<NB, CI>>>(latent, stdW, stdb);
    d_kernel<<<NB, CO>>>(convw, ncoef);
    wtrans<<<dim3(8,8), dim3(32,8)>>>(convw);
    tscale_d12<<<dim3(32,8,2), dim3(32,8)>>>(d1w, d2w, (__half*)p_w1, (__half*)p_w2);
    cudaEventRecord(ev[0], 0);

    // ---- S1: memory chain (vtrans h1, h2; otrans h1, h2) ----
    cudaStreamWaitEvent(s1, ev[0], 0);
    vtrans<<<dim3(64,256), 256, 0, s1>>>(data, 0);
    cudaEventRecord(ev[1], s1);
    vtrans<<<dim3(64,256), 256, 0, s1>>>(data, 256);
    cudaEventRecord(ev[2], s1);

    // ---- S0: winograd GEMM halves ----
    cudaStreamWaitEvent(0, ev[1], 0);
    gemm_kernel<256,256,0><<<dim3(2,128,16), 256, smem>>>(V, U, nullptr, Hh);
    cudaEventRecord(ev[3], 0);
    cudaStreamWaitEvent(0, ev[2], 0);
    gemm_kernel<256,256,0><<<dim3(2,128,16), 256, smem>>>(
        V + (size_t)HTILES*256, U, nullptr, Hh + (size_t)HTILES*4096);
    cudaEventRecord(ev[4], 0);

    // ---- S1: output transforms ----
    cudaStreamWaitEvent(s1, ev[3], 0);
    otrans<<<dim3(64,256), 256, 0, s1>>>(bias, noise, ncoef, 0);
    cudaEventRecord(ev[5], s1);
    cudaStreamWaitEvent(s1, ev[4], 0);
    otrans<<<dim3(64,256), 256, 0, s1>>>(bias, noise, ncoef, 256);
    cudaEventRecord(ev[6], s1);

    // ---- S0: D1/D2 halves (joins S1 back into origin stream) ----
    cudaStreamWaitEvent(0, ev[5], 0);
    gemm_kernel<256,1024,1><<<dim3(8,512), 256, smem>>>(
        Y, (const __half*)p_w1, d1b, Hh);
    cudaStreamWaitEvent(0, ev[6], 0);
    gemm_kernel<256,1024,1><<<dim3(8,512), 256, smem>>>(
        Y + (size_t)HPIX*256, (const __half*)p_w1, d1b, Hh + (size_t)HPIX*1024);
    gemm_kernel<1024,256,2><<<dim3(2,512), 256, smem>>>(
        (const __half*)p_h, (const __half*)p_w2, d2b, (void*)out);
    gemm_kernel<1024,256,2><<<dim3(2,512), 256, smem>>>(
        Hh + (size_t)HPIX*1024, (const __half*)p_w2, d2b, (void*)(out + (size_t)HPIX*256));
}

// round 12
// speedup vs baseline: 1.1206x; 1.1206x over previous
#include <cuda_runtime.h>
#include <cuda_fp16.h>
#include <cstdint>
#include <cstddef>

#define NB 8
#define CI 256
#define CO 256
#define NL 512
#define NPIX (8*128*128)
#define NTILES 32768            // 8 * 64 * 64 winograd tiles

#define C_STD  0.0625f
#define C_CONV 0.02946278254943948f
#define C_D1   0.08838834764831845f
#define C_D2   0.04419417382415922f

// ---------------- scratch --------------------------------------------------
__device__ float  g_s[NB*CI];
__device__ float  g_d[NB*CO];
__device__ float  g_w2s[CI*CO];                 // sum over taps of (w*C_CONV)^2
__device__ int    g_nflag;
__device__ __half g_U[(size_t)16*CO*CI];        // winograd weights [p][co][ci]
__device__ __half g_V[(size_t)16*NTILES*CI];    // winograd input  [p][tile][ci]
__device__ __half g_w1T[4*CO*CO];               // D1 w [n=1024][k=256]
__device__ __half g_w2T[(size_t)CO*4*CO];       // D2 w [n=256][k=1024]
__device__ __half g_y[(size_t)NPIX*CO];         // conv out (post-lrelu)
__device__ __half g_h[(size_t)NPIX*4*CO];       // D1 out; ALSO aliased as M [p][tile][co]

// ---------------- helpers --------------------------------------------------
__device__ __forceinline__ float lrelu(float x){ return x > 0.f ? x : 0.2f*x; }

__device__ __forceinline__ void mma16(float c[4], const uint32_t a[4], const uint32_t b[2]){
    asm volatile("mma.sync.aligned.m16n8k16.row.col.f32.f16.f16.f32 "
        "{%0,%1,%2,%3}, {%4,%5,%6,%7}, {%8,%9}, {%0,%1,%2,%3};\n"
        : "+f"(c[0]), "+f"(c[1]), "+f"(c[2]), "+f"(c[3])
        : "r"(a[0]), "r"(a[1]), "r"(a[2]), "r"(a[3]), "r"(b[0]), "r"(b[1]));
}
__device__ __forceinline__ void ldsm4(uint32_t& r0, uint32_t& r1, uint32_t& r2,
                                      uint32_t& r3, uint32_t addr){
    asm volatile("ldmatrix.sync.aligned.m8n8.x4.shared.b16 {%0,%1,%2,%3}, [%4];"
        : "=r"(r0), "=r"(r1), "=r"(r2), "=r"(r3) : "r"(addr));
}
__device__ __forceinline__ void cp16(uint32_t d, const void* s, int nbytes){
    asm volatile("cp.async.ca.shared.global [%0], [%1], 16, %2;\n"
                 :: "r"(d), "l"(s), "r"(nbytes));
}
__device__ __forceinline__ void cp_commit(){ asm volatile("cp.async.commit_group;\n"); }
template<int N> __device__ __forceinline__ void cp_wait(){
    asm volatile("cp.async.wait_group %0;\n" :: "n"(N));
}

// ---------------- tile layout ----------------------------------------------
struct Tiles {
    __half A[128][72];
    __half Bt[128][72];
};

__device__ __forceinline__ void compute_tile(const Tiles& t, float acc[2][8][4],
                                             int wm, int wn, int lane){
    uint32_t aBase = (uint32_t)__cvta_generic_to_shared(&t.A[0][0]);
    uint32_t bBase = (uint32_t)__cvta_generic_to_shared(&t.Bt[0][0]);
    uint32_t aOff = aBase + (uint32_t)(((wm*32 + (lane & 15))*72 + (lane >> 4)*8)*2);
    int g = lane >> 3;
    uint32_t bOff = bBase + (uint32_t)(((wn*64 + (g >> 1)*8 + (lane & 7))*72 + (g & 1)*8)*2);
#pragma unroll
    for (int kk = 0; kk < 4; kk++){
        uint32_t a[2][4];
#pragma unroll
        for (int mt = 0; mt < 2; mt++)
            ldsm4(a[mt][0], a[mt][1], a[mt][2], a[mt][3],
                  aOff + kk*32 + mt*(16*72*2));
        uint32_t b[8][2];
#pragma unroll
        for (int nt2 = 0; nt2 < 4; nt2++){
            uint32_t r0, r1, r2, r3;
            ldsm4(r0, r1, r2, r3, bOff + kk*32 + nt2*(16*72*2));
            b[2*nt2][0] = r0; b[2*nt2][1] = r1;
            b[2*nt2+1][0] = r2; b[2*nt2+1][1] = r3;
        }
#pragma unroll
        for (int mt = 0; mt < 2; mt++)
#pragma unroll
            for (int nt = 0; nt < 8; nt++)
                mma16(acc[mt][nt], a[mt], b[nt]);
    }
}

// ---------------- prep kernels ---------------------------------------------
__global__ void s_kernel(const float* __restrict__ latent,
                         const float* __restrict__ stdW,
                         const float* __restrict__ stdb){
    if (blockIdx.x == 0 && threadIdx.x == 0) g_nflag = 0;
    int b = blockIdx.x, i = threadIdx.x;
    float a0 = 0.f, a1 = 0.f, a2 = 0.f, a3 = 0.f;
#pragma unroll 4
    for (int l = 0; l < NL; l += 4){
        a0 += latent[b*NL+l  ] * stdW[(l  )*CI+i];
        a1 += latent[b*NL+l+1] * stdW[(l+1)*CI+i];
        a2 += latent[b*NL+l+2] * stdW[(l+2)*CI+i];
        a3 += latent[b*NL+l+3] * stdW[(l+3)*CI+i];
    }
    g_s[b*CI+i] = ((a0+a1)+(a2+a3)) * C_STD + stdb[i];
}

// uses precomputed w2s (L2-resident 256KB) instead of re-reading 2.4MB weights
__global__ void d_kernel(const float* __restrict__ ncoef){
    int b = blockIdx.x, o = threadIdx.x;
    if (b == 0 && ncoef[o] != 0.f) atomicOr(&g_nflag, 1);
    float a0 = 0.f, a1 = 0.f;
#pragma unroll 8
    for (int i = 0; i < CI; i += 2){
        float s0 = g_s[b*CI+i],   s1 = g_s[b*CI+i+1];
        a0 += g_w2s[(i  )*CO + o] * s0 * s0;
        a1 += g_w2s[(i+1)*CO + o] * s1 * s1;
    }
    g_d[b*CO+o] = rsqrtf(a0 + a1 + 1e-8f);
}

__device__ __forceinline__ void tblock(const float* src, __half* dst,
                                       int R, int C, float sc, int r0, int c0){
    __shared__ float t[32][33];
    int x = threadIdx.x, y = threadIdx.y;   // 32 x 8
#pragma unroll
    for (int i = 0; i < 32; i += 8)
        t[y+i][x] = src[(size_t)(r0+y+i)*C + c0+x];
    __syncthreads();
#pragma unroll
    for (int i = 0; i < 32; i += 8)
        dst[(size_t)(c0+y+i)*R + r0+x] = __float2half_rn(t[x][y+i]*sc);
}
__global__ void tscale_d12(const float* __restrict__ d1w, const float* __restrict__ d2w,
                           __half* __restrict__ w1, __half* __restrict__ w2){
    if (blockIdx.z == 0){
        tblock(d1w, w1, 256, 1024, C_D1, blockIdx.y*32, blockIdx.x*32);
    } else {
        int flat = blockIdx.x + blockIdx.y*32;
        tblock(d2w, w2, 1024, 256, C_D2, (flat/8)*32, (flat%8)*32);
    }
}

// -------- winograd weight transform: U = G g G^T (+ w2s byproduct) ---------
__global__ void wtrans(const float* __restrict__ cw){
    __shared__ float sg[9][32][33];      // [tap][ci][co]
    int ci0 = blockIdx.x*32, co0 = blockIdx.y*32;
    int x = threadIdx.x, y = threadIdx.y;
    int tid = y*32 + x;
#pragma unroll
    for (int k = 0; k < 9; k++)
#pragma unroll
        for (int i = 0; i < 32; i += 8)
            sg[k][y+i][x] = cw[((size_t)(k*256 + ci0 + y + i))*256 + co0 + x];
    __syncthreads();
#pragma unroll
    for (int j = 0; j < 4; j++){
        int pair = tid + j*256;
        int ci = pair & 31, co = pair >> 5;
        float g[3][3];
        float w2 = 0.f;
#pragma unroll
        for (int r = 0; r < 3; r++)
#pragma unroll
            for (int c = 0; c < 3; c++){
                g[r][c] = sg[r*3+c][ci][co] * C_CONV;
                w2 += g[r][c]*g[r][c];
            }
        g_w2s[(ci0+ci)*CO + co0+co] = w2;
        float t[4][3];
#pragma unroll
        for (int c = 0; c < 3; c++){
            t[0][c] = g[0][c];
            t[1][c] = 0.5f*(g[0][c] + g[1][c] + g[2][c]);
            t[2][c] = 0.5f*(g[0][c] - g[1][c] + g[2][c]);
            t[3][c] = g[2][c];
        }
#pragma unroll
        for (int r = 0; r < 4; r++){
            float u0 = t[r][0];
            float u1 = 0.5f*(t[r][0] + t[r][1] + t[r][2]);
            float u2 = 0.5f*(t[r][0] - t[r][1] + t[r][2]);
            float u3 = t[r][2];
            int p = r*4;
            g_U[((size_t)(p+0)*256 + co0+co)*256 + ci0+ci] = __float2half_rn(u0);
            g_U[((size_t)(p+1)*256 + co0+co)*256 + ci0+ci] = __float2half_rn(u1);
            g_U[((size_t)(p+2)*256 + co0+co)*256 + ci0+ci] = __float2half_rn(u2);
            g_U[((size_t)(p+3)*256 + co0+co)*256 + ci0+ci] = __float2half_rn(u3);
        }
    }
}

// ------- winograd input transform fused with modulation: V = B^T (x*s) B ----
// grid (64, 512); 256 threads = ci; reads fp32 data
__global__ void vtrans(const float* __restrict__ data){
    int ci = threadIdx.x;
    int tx = blockIdx.x;
    int b = blockIdx.y >> 6, ty = blockIdx.y & 63;
    size_t t = (size_t)blockIdx.y*64 + tx;
    float sv = g_s[b*256 + ci];
    int ir0 = 2*ty - 1, ic0 = 2*tx - 1;
    float d[4][4];
#pragma unroll
    for (int r = 0; r < 4; r++){
        int ir = ir0 + r;
        bool rv = (unsigned)ir < 128u;
#pragma unroll
        for (int c = 0; c < 4; c++){
            int ic = ic0 + c;
            bool v = rv && ((unsigned)ic < 128u);
            d[r][c] = v ? data[((size_t)((b*128+ir)*128 + ic))*256 + ci] * sv : 0.f;
        }
    }
    float w[4][4];
#pragma unroll
    for (int c = 0; c < 4; c++){
        w[0][c] = d[0][c] - d[2][c];
        w[1][c] = d[1][c] + d[2][c];
        w[2][c] = d[2][c] - d[1][c];
        w[3][c] = d[1][c] - d[3][c];
    }
#pragma unroll
    for (int r = 0; r < 4; r++){
        float v0 = w[r][0] - w[r][2];
        float v1 = w[r][1] + w[r][2];
        float v2 = w[r][2] - w[r][1];
        float v3 = w[r][1] - w[r][3];
        int p = r*4;
        g_V[((size_t)(p+0)*NTILES + t)*256 + ci] = __float2half_rn(v0);
        g_V[((size_t)(p+1)*NTILES + t)*256 + ci] = __float2half_rn(v1);
        g_V[((size_t)(p+2)*NTILES + t)*256 + ci] = __float2half_rn(v2);
        g_V[((size_t)(p+3)*NTILES + t)*256 + ci] = __float2half_rn(v3);
    }
}

// ---------------- winograd output transform + epilogue ----------------------
// grid (64, 512); 256 threads = co. M [p][tile][co] aliased in g_h.
__global__ void otrans(const float* __restrict__ bias, const float* __restrict__ noise,
                       const float* __restrict__ ncoef){
    int co = threadIdx.x;
    int tx = blockIdx.x;
    int b = blockIdx.y >> 6, ty = blockIdx.y & 63;
    size_t t = (size_t)blockIdx.y*64 + tx;
    int nflag = g_nflag;
    float m[4][4];
#pragma unroll
    for (int p = 0; p < 16; p++)
        m[p>>2][p&3] = __half2float(g_h[((size_t)p*NTILES + t)*256 + co]);
    float z[2][4];
#pragma unroll
    for (int c = 0; c < 4; c++){
        z[0][c] = m[0][c] + m[1][c] + m[2][c];
        z[1][c] = m[1][c] - m[2][c] - m[3][c];
    }
    float dv = g_d[b*256 + co];
    float bv = bias[co];
    float cv = nflag ? ncoef[co] : 0.f;
#pragma unroll
    for (int r = 0; r < 2; r++){
        float y0 = z[r][0] + z[r][1] + z[r][2];
        float y1 = z[r][1] - z[r][2] - z[r][3];
        int row = 2*ty + r;
#pragma unroll
        for (int c = 0; c < 2; c++){
            float yv = (c == 0) ? y0 : y1;
            int col = 2*tx + c;
            size_t pix = (size_t)(b*128 + row)*128 + col;
            float o = yv*dv + bv;
            if (nflag) o += noise[pix*256 + co] * cv;
            o = lrelu(o);
            g_y[pix*256 + co] = __float2half_rn(o);
        }
    }
}

// ---------------- generic GEMM (K64, 2-stage; EPI 0=winograd M, 1=D1, 2=D2) -
template<int K>
__device__ __forceinline__ void issue_gemm(Tiles* t, const __half* A, const __half* Bw,
                                           size_t m0, int n0, int s, int tid){
#pragma unroll
    for (int j = 0; j < 4; j++){
        int lin = tid + j*256;
        int r = lin >> 3, c8 = (lin & 7) * 8;
        cp16((uint32_t)__cvta_generic_to_shared(&t->A[r][c8]),
             A + (m0 + r)*(size_t)K + s*64 + c8, 16);
        cp16((uint32_t)__cvta_generic_to_shared(&t->Bt[r][c8]),
             Bw + (size_t)(n0 + r)*K + s*64 + c8, 16);
    }
}

template<int K, int N, int EPI>
__global__ void __launch_bounds__(256,2) gemm_kernel(
    const __half* __restrict__ A, const __half* __restrict__ Bw,
    const float* __restrict__ bias, void* __restrict__ outv)
{
    extern __shared__ Tiles tiles[];
    int tid = threadIdx.x;
    size_t m0 = (size_t)blockIdx.y * 128;
    int n0 = blockIdx.x * 128;
    if (EPI == 0){
        size_t z = blockIdx.z;
        A  += z * ((size_t)NTILES*256);
        Bw += z * (256*256);
        outv = (void*)((__half*)outv + z * ((size_t)NTILES*256));
    }
    int wid = tid >> 5, lane = tid & 31;
    int wm = wid >> 1, wn = wid & 1, qr = lane >> 2, qc = lane & 3;

    float acc[2][8][4];
#pragma unroll
    for (int i = 0; i < 2; i++)
#pragma unroll
        for (int j = 0; j < 8; j++)
#pragma unroll
            for (int k = 0; k < 4; k++) acc[i][j][k] = 0.f;

    const int NK = K/64;
    issue_gemm<K>(&tiles[0], A, Bw, m0, n0, 0, tid); cp_commit();
#pragma unroll 1
    for (int s = 0; s < NK; s++){
        cp_wait<0>();
        __syncthreads();
        if (s + 1 < NK){ issue_gemm<K>(&tiles[(s+1)&1], A, Bw, m0, n0, s+1, tid); cp_commit(); }
        compute_tile(tiles[s&1], acc, wm, wn, lane);
    }

#pragma unroll
    for (int mt = 0; mt < 2; mt++){
#pragma unroll
        for (int nt = 0; nt < 8; nt++){
            int col = n0 + wn*64 + nt*8 + 2*qc;
            float b0 = (EPI != 0) ? bias[col]   : 0.f;
            float b1 = (EPI != 0) ? bias[col+1] : 0.f;
#pragma unroll
            for (int r2 = 0; r2 < 2; r2++){
                size_t m = m0 + wm*32 + mt*16 + qr + r2*8;
                float v0 = acc[mt][nt][r2*2+0];
                float v1 = acc[mt][nt][r2*2+1];
                if (EPI != 0){ v0 = lrelu(v0 + b0); v1 = lrelu(v1 + b1); }
                if (EPI == 2){
                    *(float2*)((float*)outv + m*(size_t)N + col) = make_float2(v0, v1);
                } else {
                    __half2 hv = __floats2half2_rn(v0, v1);
                    *(uint32_t*)((__half*)outv + m*(size_t)N + col) = *(uint32_t*)&hv;
                }
            }
        }
    }
}

// ---------------- launch ----------------------------------------------------
extern "C" void kernel_launch(void* const* d_in, const int* in_sizes, int n_in,
                              void* d_out, int out_size){
    const float* data   = (const float*)d_in[0];
    const float* latent = (const float*)d_in[1];
    const float* noise  = (const float*)d_in[2];
    const float* stdW   = (const float*)d_in[3];
    const float* stdb   = (const float*)d_in[4];
    const float* convw  = (const float*)d_in[5];
    const float* bias   = (const float*)d_in[6];
    const float* ncoef  = (const float*)d_in[7];
    const float* d1w    = (const float*)d_in[8];
    const float* d1b    = (const float*)d_in[9];
    const float* d2w    = (const float*)d_in[10];
    const float* d2b    = (const float*)d_in[11];
    float* out = (float*)d_out;

    void *p_U, *p_V, *p_w1, *p_w2, *p_y, *p_h;
    cudaGetSymbolAddress(&p_U,  g_U);
    cudaGetSymbolAddress(&p_V,  g_V);
    cudaGetSymbolAddress(&p_w1, g_w1T);
    cudaGetSymbolAddress(&p_w2, g_w2T);
    cudaGetSymbolAddress(&p_y,  g_y);
    cudaGetSymbolAddress(&p_h,  g_h);

    int smem = (int)sizeof(Tiles) * 2;   // 73728 B
    cudaFuncSetAttribute(gemm_kernel<256,256,0>,  cudaFuncAttributeMaxDynamicSharedMemorySize, smem);
    cudaFuncSetAttribute(gemm_kernel<256,1024,1>, cudaFuncAttributeMaxDynamicSharedMemorySize, smem);
    cudaFuncSetAttribute(gemm_kernel<1024,256,2>, cudaFuncAttributeMaxDynamicSharedMemorySize, smem);

    // ncu -s 5 -c 1 profiles the 6th launch = batched winograd GEMM
    s_kernel<<<NB, CI>>>(latent, stdW, stdb);
    wtrans<<<dim3(8,8), dim3(32,8)>>>(convw);
    d_kernel<<<NB, CO>>>(ncoef);
    tscale_d12<<<dim3(32,8,2), dim3(32,8)>>>(d1w, d2w, (__half*)p_w1, (__half*)p_w2);
    vtrans<<<dim3(64,512), 256>>>(data);
    gemm_kernel<256,256,0><<<dim3(2,256,16), 256, smem>>>(
        (const __half*)p_V, (const __half*)p_U, nullptr, p_h);
    otrans<<<dim3(64,512), 256>>>(bias, noise, ncoef);
    gemm_kernel<256,1024,1><<<dim3(8,1024), 256, smem>>>(
        (const __half*)p_y, (const __half*)p_w1, d1b, p_h);
    gemm_kernel<1024,256,2><<<dim3(2,1024), 256, smem>>>(
        (const __half*)p_h, (const __half*)p_w2, d2b, (void*)out);
}